// round 6
// baseline (speedup 1.0000x reference)
#include <cuda_runtime.h>
#include <math.h>

#define B 8
#define N 256
#define BN 2048
#define NID 64
#define V 128
#define GH 128
#define PHI 256
#define RHO 128
#define EPS 1e-5f

// ---------------- scratch ----------------
__device__ float g_H[BN * GH];
__device__ float g_H2[BN * GH];
__device__ float g_phi[BN * PHI];
__device__ float g_sums[8 * 2 * B * PHI];
__device__ float g_msk[BN * N];      // sign(A) in {-1,0,1}, layout [b][i][j]
__device__ float2 g_rcp[BN];         // (1/max(cntPos,1), 1/max(cntNeg,1)) per target j

// ---------------- K0: prep  masks + counts ----------------
__global__ void k_prep(const float* __restrict__ A) {
    int b = blockIdx.x, jc = blockIdx.y * 32;
    int t = threadIdx.x;              // 256
    int j = jc + (t & 31), iseg = t >> 5;   // 8 segs of 32 i
    const float* Ab = A + b * N * N;
    float cp = 0.f, cn = 0.f;
#pragma unroll 4
    for (int ii = 0; ii < 32; ii++) {
        int i = iseg * 32 + ii;
        float a = Ab[i * N + j];
        float p = (a > 0.f) ? 1.f : 0.f;
        float n = (a < 0.f) ? 1.f : 0.f;
        cp += p; cn += n;
        g_msk[((b << 8) + i) * N + j] = p - n;
    }
    __shared__ float sp[8][32], sn[8][32];
    sp[iseg][t & 31] = cp; sn[iseg][t & 31] = cn;
    __syncthreads();
    if (t < 32) {
        float tp = 0.f, tn = 0.f;
#pragma unroll
        for (int s = 0; s < 8; s++) { tp += sp[s][t]; tn += sn[s][t]; }
        g_rcp[(b << 8) + jc + t] = make_float2(1.f / fmaxf(tp, 1.f), 1.f / fmaxf(tn, 1.f));
    }
}

// ---------------- K1: embedding (512 thr, 8 rows, 2 rows/thread) ----------------
__global__ void __launch_bounds__(512) k_emb(const float* __restrict__ X,
                      const float* __restrict__ W1, const float* __restrict__ b1,
                      const float* __restrict__ W2, const float* __restrict__ b2) {
    int r0 = blockIdx.x * 8;
    int t = threadIdx.x;
    int col = t & 127, rg = t >> 7;   // rg 0..3, rows rg*2, rg*2+1
    __shared__ __align__(16) float xsT[NID * 12];
    __shared__ __align__(16) float h1T[V * 12];

    if (t < 8 * NID) {
        int rr = t >> 6, kk = t & 63;
        xsT[kk * 12 + rr] = X[(r0 + rr) * NID + kk];
    }
    __syncthreads();
    float a0, a1;
    a0 = a1 = b1[col];
#pragma unroll 8
    for (int k = 0; k < NID; k++) {
        float w = W1[k * V + col];
        float2 x = *(const float2*)&xsT[k * 12 + rg * 2];
        a0 = fmaf(x.x, w, a0); a1 = fmaf(x.y, w, a1);
    }
    *(float2*)&h1T[col * 12 + rg * 2] = make_float2(fmaxf(a0, 0.f), fmaxf(a1, 0.f));
    __syncthreads();
    a0 = a1 = b2[col];
#pragma unroll 8
    for (int k = 0; k < V; k++) {
        float w = W2[k * V + col];
        float2 x = *(const float2*)&h1T[k * 12 + rg * 2];
        a0 = fmaf(x.x, w, a0); a1 = fmaf(x.y, w, a1);
    }
    int base = (r0 + rg * 2) * V + col;
    g_H[base] = a0; g_H[base + V] = a1;
}

// ---------------- K2: fused RGCN (reduce 1024 thr / matmul 512 thr) ----------------
// block = (b, j-tile of 8); 1024 threads = 8 i-segments x 128 cols
__global__ void __launch_bounds__(1024) k_rgcn(const float* __restrict__ Wrel,
                                               const float* __restrict__ Wroot,
                                               const float* __restrict__ bias) {
    int b = blockIdx.x >> 5;
    int j0 = (blockIdx.x & 31) * 8;
    int t = threadIdx.x;
    int col = t & 127, iseg = t >> 7;     // 0..7
    __shared__ __align__(16) float msk_s[N][8];                 // 8KB
    __shared__ float s1S[8][128], s1A[8][128];                  // 8KB
    __shared__ float s2S[8][128], s2A[8][128];                  // 8KB
    __shared__ __align__(16) float hrT[GH * 12];                // 6KB
    __shared__ __align__(16) float snT[GH * 12];
    __shared__ __align__(16) float spT[GH * 12];
    __shared__ float2 rcp_s[8];

    for (int idx = t; idx < N * 8; idx += 1024) {
        int i = idx >> 3, jj = idx & 7;
        msk_s[i][jj] = g_msk[((b << 8) + i) * N + j0 + jj];
    }
    if (t < 8) rcp_s[t] = g_rcp[(b << 8) + j0 + t];
    __syncthreads();

    float accS[8], accA[8];
#pragma unroll
    for (int jj = 0; jj < 8; jj++) { accS[jj] = 0.f; accA[jj] = 0.f; }
    const float* Hb = g_H + ((b << 8) + (iseg << 5)) * V + col;
#pragma unroll 8
    for (int ii = 0; ii < 32; ii++) {
        float h = Hb[ii * V];
        int i = (iseg << 5) + ii;
        float4 m1 = *(const float4*)&msk_s[i][0];
        float4 m2 = *(const float4*)&msk_s[i][4];
        accS[0] = fmaf(m1.x, h, accS[0]); accA[0] = fmaf(fabsf(m1.x), h, accA[0]);
        accS[1] = fmaf(m1.y, h, accS[1]); accA[1] = fmaf(fabsf(m1.y), h, accA[1]);
        accS[2] = fmaf(m1.z, h, accS[2]); accA[2] = fmaf(fabsf(m1.z), h, accA[2]);
        accS[3] = fmaf(m1.w, h, accS[3]); accA[3] = fmaf(fabsf(m1.w), h, accA[3]);
        accS[4] = fmaf(m2.x, h, accS[4]); accA[4] = fmaf(fabsf(m2.x), h, accA[4]);
        accS[5] = fmaf(m2.y, h, accS[5]); accA[5] = fmaf(fabsf(m2.y), h, accA[5]);
        accS[6] = fmaf(m2.z, h, accS[6]); accA[6] = fmaf(fabsf(m2.z), h, accA[6]);
        accS[7] = fmaf(m2.w, h, accS[7]); accA[7] = fmaf(fabsf(m2.w), h, accA[7]);
    }
    // dual-buffer 4-pass combine: segs 0-3 -> s1, segs 4-7 -> s2 (parallel)
#pragma unroll
    for (int s = 0; s < 4; s++) {
        if (iseg == s) {
            if (s == 0) {
#pragma unroll
                for (int jj = 0; jj < 8; jj++) { s1S[jj][col] = accS[jj]; s1A[jj][col] = accA[jj]; }
            } else {
#pragma unroll
                for (int jj = 0; jj < 8; jj++) { s1S[jj][col] += accS[jj]; s1A[jj][col] += accA[jj]; }
            }
        }
        if (iseg == s + 4) {
            if (s == 0) {
#pragma unroll
                for (int jj = 0; jj < 8; jj++) { s2S[jj][col] = accS[jj]; s2A[jj][col] = accA[jj]; }
            } else {
#pragma unroll
                for (int jj = 0; jj < 8; jj++) { s2S[jj][col] += accS[jj]; s2A[jj][col] += accA[jj]; }
            }
        }
        __syncthreads();
    }
    // normalize + transpose (iseg 0); stage H rows (all threads)
    if (iseg == 0) {
#pragma unroll
        for (int jj = 0; jj < 8; jj++) {
            float sa = s1A[jj][col] + s2A[jj][col];
            float ss = s1S[jj][col] + s2S[jj][col];
            spT[col * 12 + jj] = (sa + ss) * 0.5f * rcp_s[jj].x;
            snT[col * 12 + jj] = (sa - ss) * 0.5f * rcp_s[jj].y;
        }
    }
    if (t < 8 * GH) {
        int rr = t >> 7, kk = t & 127;
        hrT[kk * 12 + rr] = g_H[((b << 8) + j0 + rr) * GH + kk];
    }
    __syncthreads();

    // matmul on lower 512 threads: rg2 handles rows rg2*2, rg2*2+1
    if (t < 512) {
        int rg2 = t >> 7;
        const float* W0 = Wrel;
        const float* W1 = Wrel + V * GH;
        float a0, a1;
        a0 = a1 = bias[col];
#pragma unroll 4
        for (int k = 0; k < GH; k++) {
            float wr = Wroot[k * GH + col];
            float w0 = W0[k * GH + col];
            float w1 = W1[k * GH + col];
            float2 h = *(const float2*)&hrT[k * 12 + rg2 * 2];
            float2 sn = *(const float2*)&snT[k * 12 + rg2 * 2];
            float2 sp = *(const float2*)&spT[k * 12 + rg2 * 2];
            a0 = fmaf(h.x, wr, a0);  a1 = fmaf(h.y, wr, a1);
            a0 = fmaf(sn.x, w0, a0); a1 = fmaf(sn.y, w0, a1);
            a0 = fmaf(sp.x, w1, a0); a1 = fmaf(sp.y, w1, a1);
        }
        int base = ((b << 8) + j0 + rg2 * 2) * GH + col;
        g_H2[base] = a0; g_H2[base + GH] = a1;
    }
}

// ---------------- K3: fused scatter + layernorm + MLP + H+= ----------------
// block = (b, i-tile of 8); 1024 threads = 8 j-segments x 128 cols
__global__ void __launch_bounds__(1024) k_scat(const float* __restrict__ A,
                                               const float* __restrict__ norm_g, const float* __restrict__ norm_b,
                                               const float* __restrict__ law, const float* __restrict__ lab,
                                               const float* __restrict__ lbw, const float* __restrict__ lbb) {
    int b = blockIdx.x >> 5;
    int i0 = (blockIdx.x & 31) * 8;
    int t = threadIdx.x;
    int col = t & 127, jseg = t >> 7;     // 0..7
    int wp = t >> 5, lane = t & 31;
    __shared__ __align__(16) float aabT[N * 8];     // [j][i-in-tile] 8KB
    __shared__ float b1f[8][128], b2f[8][128];      // 8KB
    __shared__ __align__(16) float bufT[GH * 12];   // 6KB
    __shared__ float stat[8][2];

    // stage |A| transposed: aabT[j][q] = |A[b][i0+q][j]|
    {
        int jj = t & 255, half = t >> 8;   // half 0..3 -> rows half*2, half*2+1
        const float* Ar = A + (b * N + i0 + half * 2) * N + jj;
        *(float2*)&aabT[jj * 8 + half * 2] = make_float2(fabsf(Ar[0]), fabsf(Ar[N]));
    }
    __syncthreads();

    float acc[8];
#pragma unroll
    for (int q = 0; q < 8; q++) acc[q] = 0.f;
    const float* H2b = g_H2 + ((b << 8) + (jseg << 5)) * GH + col;
#pragma unroll 8
    for (int jj = 0; jj < 32; jj++) {
        float h2 = H2b[jj * GH];
        int j = (jseg << 5) + jj;
        float4 m1 = *(const float4*)&aabT[j * 8];
        float4 m2 = *(const float4*)&aabT[j * 8 + 4];
        acc[0] = fmaf(m1.x, h2, acc[0]); acc[1] = fmaf(m1.y, h2, acc[1]);
        acc[2] = fmaf(m1.z, h2, acc[2]); acc[3] = fmaf(m1.w, h2, acc[3]);
        acc[4] = fmaf(m2.x, h2, acc[4]); acc[5] = fmaf(m2.y, h2, acc[5]);
        acc[6] = fmaf(m2.z, h2, acc[6]); acc[7] = fmaf(m2.w, h2, acc[7]);
    }
#pragma unroll
    for (int s = 0; s < 4; s++) {
        if (jseg == s) {
            if (s == 0) {
#pragma unroll
                for (int q = 0; q < 8; q++) b1f[q][col] = acc[q];
            } else {
#pragma unroll
                for (int q = 0; q < 8; q++) b1f[q][col] += acc[q];
            }
        }
        if (jseg == s + 4) {
            if (s == 0) {
#pragma unroll
                for (int q = 0; q < 8; q++) b2f[q][col] = acc[q];
            } else {
#pragma unroll
                for (int q = 0; q < 8; q++) b2f[q][col] += acc[q];
            }
        }
        __syncthreads();
    }

    // layernorm stats: warps 0..7 -> row wp
    if (wp < 8) {
        float s = 0.f, sq = 0.f;
#pragma unroll
        for (int c = 0; c < 4; c++) {
            float v = b1f[wp][lane + c * 32] + b2f[wp][lane + c * 32];
            s += v; sq = fmaf(v, v, sq);
        }
#pragma unroll
        for (int o = 16; o > 0; o >>= 1) {
            s += __shfl_xor_sync(0xffffffff, s, o);
            sq += __shfl_xor_sync(0xffffffff, sq, o);
        }
        if (lane == 0) {
            float mean = s * (1.f / GH);
            float var = sq * (1.f / GH) - mean * mean;
            stat[wp][0] = mean;
            stat[wp][1] = rsqrtf(var + EPS);
        }
    }
    __syncthreads();
    // normalize + relu + transpose into bufT (1024 threads, one elem each)
    {
        int r = t & 7, cc = t >> 3;
        float v = (b1f[r][cc] + b2f[r][cc] - stat[r][0]) * stat[r][1] * norm_g[cc] + norm_b[cc];
        bufT[cc * 12 + r] = fmaxf(v, 0.f);
    }
    __syncthreads();

    // MLP on lower 512 threads
    if (t < 512) {
        int rg2 = t >> 7;
        float a0, a1;
        a0 = a1 = lab[col];
#pragma unroll 8
        for (int k = 0; k < GH; k++) {
            float w = law[k * GH + col];
            float2 x = *(const float2*)&bufT[k * 12 + rg2 * 2];
            a0 = fmaf(x.x, w, a0); a1 = fmaf(x.y, w, a1);
        }
        __syncthreads();
        *(float2*)&bufT[col * 12 + rg2 * 2] = make_float2(fmaxf(a0, 0.f), fmaxf(a1, 0.f));
        __syncthreads();

        a0 = a1 = lbb[col];
#pragma unroll 8
        for (int k = 0; k < GH; k++) {
            float w = lbw[k * GH + col];
            float2 x = *(const float2*)&bufT[k * 12 + rg2 * 2];
            a0 = fmaf(x.x, w, a0); a1 = fmaf(x.y, w, a1);
        }
        int base = ((b << 8) + i0 + rg2 * 2) * GH + col;
        g_H[base] += a0; g_H[base + GH] += a1;
    } else {
        __syncthreads();
        __syncthreads();
    }
}

// ---------------- K4: phi MLP (1024 threads, 8 rows, 2 rows/thread) ----------------
__global__ void __launch_bounds__(1024) k_phi(const float* __restrict__ w1, const float* __restrict__ b1,
                                              const float* __restrict__ w2, const float* __restrict__ b2) {
    int r0 = blockIdx.x * 8;
    int t = threadIdx.x;
    int col = t & 255, rg = t >> 8;   // rg 0..3, rows rg*2, rg*2+1
    __shared__ __align__(16) float hT[GH * 12];
    __shared__ __align__(16) float h1T[PHI * 12];

    {   // 1024 threads = 8*128 exactly
        int rr = t >> 7, kk = t & 127;
        hT[kk * 12 + rr] = g_H[(r0 + rr) * GH + kk];
    }
    __syncthreads();
    float a0, a1;
    a0 = a1 = b1[col];
#pragma unroll 8
    for (int k = 0; k < GH; k++) {
        float w = w1[k * PHI + col];
        float2 x = *(const float2*)&hT[k * 12 + rg * 2];
        a0 = fmaf(x.x, w, a0); a1 = fmaf(x.y, w, a1);
    }
    *(float2*)&h1T[col * 12 + rg * 2] = make_float2(fmaxf(a0, 0.f), fmaxf(a1, 0.f));
    __syncthreads();
    a0 = a1 = b2[col];
#pragma unroll 8
    for (int k = 0; k < PHI; k++) {
        float w = w2[k * PHI + col];
        float2 x = *(const float2*)&h1T[k * 12 + rg * 2];
        a0 = fmaf(x.x, w, a0); a1 = fmaf(x.y, w, a1);
    }
    int base = (r0 + rg * 2) * PHI + col;
    g_phi[base] = fmaxf(a0, 0.f);
    g_phi[base + PHI] = fmaxf(a1, 0.f);
}

// ---------------- K5: masked pooling (8 segments of 32 nodes) ----------------
__global__ void k_pool(const float* __restrict__ home_mask) {
    int b = blockIdx.x;
    int seg = blockIdx.y;
    int p = threadIdx.x;          // 256
    const float* pb = g_phi + b * N * PHI;
    const float* hm = home_mask + b * N;
    float hs = 0.f, as = 0.f;
    int n0 = seg * 32;
#pragma unroll 8
    for (int n = n0; n < n0 + 32; n++) {
        float v = pb[n * PHI + p];
        float m = hm[n];
        hs = fmaf(v, m, hs);
        as = fmaf(v, 1.f - m, as);
    }
    g_sums[((seg * 2 + 0) * B + b) * PHI + p] = hs;
    g_sums[((seg * 2 + 1) * B + b) * PHI + p] = as;
}

// ---------------- K6: rho head ----------------
__global__ void k_rho(const float* __restrict__ w1, const float* __restrict__ b1,
                      const float* __restrict__ w2, float* __restrict__ out) {
    int b = blockIdx.x;           // 8
    int t = threadIdx.x;          // 128
    __shared__ float hs[PHI];
    __shared__ float as[PHI];
    __shared__ float red[RHO];
    for (int c = t; c < PHI; c += 128) {
        float h = 0.f, a = 0.f;
#pragma unroll
        for (int seg = 0; seg < 8; seg++) {
            h += g_sums[((seg * 2 + 0) * B + b) * PHI + c];
            a += g_sums[((seg * 2 + 1) * B + b) * PHI + c];
        }
        hs[c] = h; as[c] = a;
    }
    __syncthreads();
    float rh = b1[t], ra = b1[t];
#pragma unroll 8
    for (int k = 0; k < PHI; k++) {
        float w = w1[k * RHO + t];
        rh = fmaf(hs[k], w, rh);
        ra = fmaf(as[k], w, ra);
    }
    rh = fmaxf(rh, 0.f);
    ra = fmaxf(ra, 0.f);
    red[t] = (rh - ra) * w2[t];
    __syncthreads();
    for (int s = RHO / 2; s > 0; s >>= 1) {
        if (t < s) red[t] += red[t + s];
        __syncthreads();
    }
    if (t == 0) out[b] = 0.5f + 0.5f * tanhf(red[0]);
}

// ---------------- launch ----------------
extern "C" void kernel_launch(void* const* d_in, const int* in_sizes, int n_in,
                              void* d_out, int out_size) {
    const float* A        = (const float*)d_in[0];
    const float* X        = (const float*)d_in[1];
    const float* home     = (const float*)d_in[2];
    const float* emb1_w   = (const float*)d_in[3];
    const float* emb1_b   = (const float*)d_in[4];
    const float* emb2_w   = (const float*)d_in[5];
    const float* emb2_b   = (const float*)d_in[6];
    const float* rgcn_w0  = (const float*)d_in[7];
    const float* root0    = (const float*)d_in[8];
    const float* bias0    = (const float*)d_in[9];
    const float* law0     = (const float*)d_in[10];
    const float* lab0     = (const float*)d_in[11];
    const float* lbw0     = (const float*)d_in[12];
    const float* lbb0     = (const float*)d_in[13];
    const float* rgcn_w1  = (const float*)d_in[14];
    const float* root1    = (const float*)d_in[15];
    const float* bias1    = (const float*)d_in[16];
    const float* law1     = (const float*)d_in[17];
    const float* lab1     = (const float*)d_in[18];
    const float* lbw1     = (const float*)d_in[19];
    const float* lbb1     = (const float*)d_in[20];
    const float* norm_g   = (const float*)d_in[21];
    const float* norm_b   = (const float*)d_in[22];
    const float* phi_w1   = (const float*)d_in[23];
    const float* phi_b1   = (const float*)d_in[24];
    const float* phi_w2   = (const float*)d_in[25];
    const float* phi_b2   = (const float*)d_in[26];
    const float* rho_w1   = (const float*)d_in[27];
    const float* rho_b1   = (const float*)d_in[28];
    const float* rho_w2   = (const float*)d_in[29];
    float* out = (float*)d_out;

    dim3 pgrid(8, 8);
    k_prep<<<pgrid, 256>>>(A);
    k_emb<<<256, 512>>>(X, emb1_w, emb1_b, emb2_w, emb2_b);

    k_rgcn<<<256, 1024>>>(rgcn_w0, root0, bias0);
    k_scat<<<256, 1024>>>(A, norm_g, norm_b, law0, lab0, lbw0, lbb0);

    k_rgcn<<<256, 1024>>>(rgcn_w1, root1, bias1);
    k_scat<<<256, 1024>>>(A, norm_g, norm_b, law1, lab1, lbw1, lbb1);

    k_phi<<<256, 1024>>>(phi_w1, phi_b1, phi_w2, phi_b2);
    dim3 pg(B, 8);
    k_pool<<<pg, 256>>>(home);
    k_rho<<<B, 128>>>(rho_w1, rho_b1, rho_w2, out);
}

// round 7
// speedup vs baseline: 1.1703x; 1.1703x over previous
#include <cuda_runtime.h>
#include <math.h>

#define B 8
#define N 256
#define BN 2048
#define NID 64
#define V 128
#define GH 128
#define PHI 256
#define RHO 128
#define EPS 1e-5f

// ---------------- scratch ----------------
__device__ float g_H[BN * GH];
__device__ float g_H2[BN * GH];
__device__ float g_phi[BN * PHI];
__device__ float g_sums[8 * 2 * B * PHI];
__device__ float g_msk[BN * N];      // sign(A) in {-1,0,1}, layout [b][i][j]
__device__ float2 g_rcp[BN];         // (1/max(cntPos,1), 1/max(cntNeg,1)) per target j

// ---------------- K0: prep  masks + counts ----------------
__global__ void k_prep(const float* __restrict__ A) {
    int b = blockIdx.x, jc = blockIdx.y * 32;
    int t = threadIdx.x;              // 256
    int j = jc + (t & 31), iseg = t >> 5;   // 8 segs of 32 i
    const float* Ab = A + b * N * N;
    float cp = 0.f, cn = 0.f;
#pragma unroll 4
    for (int ii = 0; ii < 32; ii++) {
        int i = iseg * 32 + ii;
        float a = Ab[i * N + j];
        float p = (a > 0.f) ? 1.f : 0.f;
        float n = (a < 0.f) ? 1.f : 0.f;
        cp += p; cn += n;
        g_msk[((b << 8) + i) * N + j] = p - n;
    }
    __shared__ float sp[8][32], sn[8][32];
    sp[iseg][t & 31] = cp; sn[iseg][t & 31] = cn;
    __syncthreads();
    if (t < 32) {
        float tp = 0.f, tn = 0.f;
#pragma unroll
        for (int s = 0; s < 8; s++) { tp += sp[s][t]; tn += sn[s][t]; }
        g_rcp[(b << 8) + jc + t] = make_float2(1.f / fmaxf(tp, 1.f), 1.f / fmaxf(tn, 1.f));
    }
}

// ---------------- K1: embedding (512 thr, 8 rows, 2 rows/thread) ----------------
__global__ void __launch_bounds__(512) k_emb(const float* __restrict__ X,
                      const float* __restrict__ W1, const float* __restrict__ b1,
                      const float* __restrict__ W2, const float* __restrict__ b2) {
    int r0 = blockIdx.x * 8;
    int t = threadIdx.x;
    int col = t & 127, rg = t >> 7;   // rg 0..3, rows rg*2, rg*2+1
    __shared__ __align__(16) float xsT[NID * 12];
    __shared__ __align__(16) float h1T[V * 12];

    if (t < 8 * NID) {
        int rr = t >> 6, kk = t & 63;
        xsT[kk * 12 + rr] = X[(r0 + rr) * NID + kk];
    }
    __syncthreads();
    float a0, a1;
    a0 = a1 = b1[col];
#pragma unroll 8
    for (int k = 0; k < NID; k++) {
        float w = W1[k * V + col];
        float2 x = *(const float2*)&xsT[k * 12 + rg * 2];
        a0 = fmaf(x.x, w, a0); a1 = fmaf(x.y, w, a1);
    }
    *(float2*)&h1T[col * 12 + rg * 2] = make_float2(fmaxf(a0, 0.f), fmaxf(a1, 0.f));
    __syncthreads();
    a0 = a1 = b2[col];
#pragma unroll 8
    for (int k = 0; k < V; k++) {
        float w = W2[k * V + col];
        float2 x = *(const float2*)&h1T[k * 12 + rg * 2];
        a0 = fmaf(x.x, w, a0); a1 = fmaf(x.y, w, a1);
    }
    int base = (r0 + rg * 2) * V + col;
    g_H[base] = a0; g_H[base + V] = a1;
}

// ---------------- K2: fused RGCN (masked-mean reduce + 3-way matmul) ----------------
// block = (b, j-tile of 8); 512 threads = 4 i-segments x 128 cols
__global__ void __launch_bounds__(512) k_rgcn(const float* __restrict__ Wrel,
                                              const float* __restrict__ Wroot,
                                              const float* __restrict__ bias) {
    int b = blockIdx.x >> 5;
    int j0 = (blockIdx.x & 31) * 8;
    int t = threadIdx.x;
    int col = t & 127, iseg = t >> 7;     // 0..3
    __shared__ __align__(16) float msk_s[N][8];     // 8KB
    __shared__ float sAccS[8][128], sAccA[8][128];  // 8KB
    __shared__ __align__(16) float hrT[GH * 12];    // 6KB
    __shared__ __align__(16) float snT[GH * 12];
    __shared__ __align__(16) float spT[GH * 12];
    __shared__ float2 rcp_s[8];

    for (int idx = t; idx < N * 8; idx += 512) {
        int i = idx >> 3, jj = idx & 7;
        msk_s[i][jj] = g_msk[((b << 8) + i) * N + j0 + jj];
    }
    if (t < 8) rcp_s[t] = g_rcp[(b << 8) + j0 + t];
    __syncthreads();

    float accS[8], accA[8];
#pragma unroll
    for (int jj = 0; jj < 8; jj++) { accS[jj] = 0.f; accA[jj] = 0.f; }
    const float* Hb = g_H + ((b << 8) + (iseg << 6)) * V + col;
#pragma unroll 16
    for (int ii = 0; ii < 64; ii++) {
        float h = Hb[ii * V];
        int i = (iseg << 6) + ii;
        float4 m1 = *(const float4*)&msk_s[i][0];
        float4 m2 = *(const float4*)&msk_s[i][4];
        accS[0] = fmaf(m1.x, h, accS[0]); accA[0] = fmaf(fabsf(m1.x), h, accA[0]);
        accS[1] = fmaf(m1.y, h, accS[1]); accA[1] = fmaf(fabsf(m1.y), h, accA[1]);
        accS[2] = fmaf(m1.z, h, accS[2]); accA[2] = fmaf(fabsf(m1.z), h, accA[2]);
        accS[3] = fmaf(m1.w, h, accS[3]); accA[3] = fmaf(fabsf(m1.w), h, accA[3]);
        accS[4] = fmaf(m2.x, h, accS[4]); accA[4] = fmaf(fabsf(m2.x), h, accA[4]);
        accS[5] = fmaf(m2.y, h, accS[5]); accA[5] = fmaf(fabsf(m2.y), h, accA[5]);
        accS[6] = fmaf(m2.z, h, accS[6]); accA[6] = fmaf(fabsf(m2.z), h, accA[6]);
        accS[7] = fmaf(m2.w, h, accS[7]); accA[7] = fmaf(fabsf(m2.w), h, accA[7]);
    }
    // 4-pass combine into sAcc
#pragma unroll
    for (int s = 0; s < 4; s++) {
        if (iseg == s) {
            if (s == 0) {
#pragma unroll
                for (int jj = 0; jj < 8; jj++) { sAccS[jj][col] = accS[jj]; sAccA[jj][col] = accA[jj]; }
            } else {
#pragma unroll
                for (int jj = 0; jj < 8; jj++) { sAccS[jj][col] += accS[jj]; sAccA[jj][col] += accA[jj]; }
            }
        }
        __syncthreads();
    }
    // normalize + transpose (iseg 0), stage H rows (all threads)
    if (iseg == 0) {
#pragma unroll
        for (int jj = 0; jj < 8; jj++) {
            float sa = sAccA[jj][col], ss = sAccS[jj][col];
            spT[col * 12 + jj] = (sa + ss) * 0.5f * rcp_s[jj].x;
            snT[col * 12 + jj] = (sa - ss) * 0.5f * rcp_s[jj].y;
        }
    }
    for (int idx = t; idx < 8 * GH; idx += 512) {
        int rr = idx >> 7, kk = idx & 127;
        hrT[kk * 12 + rr] = g_H[((b << 8) + j0 + rr) * GH + kk];
    }
    __syncthreads();

    // matmul: rg = iseg handles rows rg*2, rg*2+1
    const float* W0 = Wrel;
    const float* W1 = Wrel + V * GH;
    float a0, a1;
    a0 = a1 = bias[col];
#pragma unroll 8
    for (int k = 0; k < GH; k++) {
        float wr = Wroot[k * GH + col];
        float w0 = W0[k * GH + col];
        float w1 = W1[k * GH + col];
        float2 h = *(const float2*)&hrT[k * 12 + iseg * 2];
        float2 sn = *(const float2*)&snT[k * 12 + iseg * 2];
        float2 sp = *(const float2*)&spT[k * 12 + iseg * 2];
        a0 = fmaf(h.x, wr, a0);  a1 = fmaf(h.y, wr, a1);
        a0 = fmaf(sn.x, w0, a0); a1 = fmaf(sn.y, w0, a1);
        a0 = fmaf(sp.x, w1, a0); a1 = fmaf(sp.y, w1, a1);
    }
    int base = ((b << 8) + j0 + iseg * 2) * GH + col;
    g_H2[base] = a0; g_H2[base + GH] = a1;
}

// ---------------- K3: fused scatter + layernorm + MLP + H+= ----------------
// block = (b, i-tile of 8); 512 threads = 4 j-segments x 128 cols
__global__ void __launch_bounds__(512) k_scat(const float* __restrict__ A,
                                              const float* __restrict__ norm_g, const float* __restrict__ norm_b,
                                              const float* __restrict__ law, const float* __restrict__ lab,
                                              const float* __restrict__ lbw, const float* __restrict__ lbb) {
    int b = blockIdx.x >> 5;
    int i0 = (blockIdx.x & 31) * 8;
    int t = threadIdx.x;
    int col = t & 127, jseg = t >> 7;     // 0..3
    int wp = t >> 5, lane = t & 31;
    __shared__ __align__(16) float aabT[N * 8];     // [j][i-in-tile] 8KB
    __shared__ float buf[8][128];                   // 4KB
    __shared__ __align__(16) float bufT[GH * 12];   // 6KB
    __shared__ float stat[8][2];

    // stage |A| transposed: aabT[j][q] = |A[b][i0+q][j]|
    {
        int jj = t & 255, half = t >> 8;   // half: rows 0-3 / 4-7
        const float* Ar = A + (b * N + i0 + half * 4) * N + jj;
        float a_[4];
#pragma unroll
        for (int q = 0; q < 4; q++) a_[q] = fabsf(Ar[q * N]);
        *(float4*)&aabT[jj * 8 + half * 4] = make_float4(a_[0], a_[1], a_[2], a_[3]);
    }
    __syncthreads();

    float acc[8];
#pragma unroll
    for (int q = 0; q < 8; q++) acc[q] = 0.f;
    const float* H2b = g_H2 + ((b << 8) + (jseg << 6)) * GH + col;
#pragma unroll 16
    for (int jj = 0; jj < 64; jj++) {
        float h2 = H2b[jj * GH];
        int j = (jseg << 6) + jj;
        float4 m1 = *(const float4*)&aabT[j * 8];
        float4 m2 = *(const float4*)&aabT[j * 8 + 4];
        acc[0] = fmaf(m1.x, h2, acc[0]); acc[1] = fmaf(m1.y, h2, acc[1]);
        acc[2] = fmaf(m1.z, h2, acc[2]); acc[3] = fmaf(m1.w, h2, acc[3]);
        acc[4] = fmaf(m2.x, h2, acc[4]); acc[5] = fmaf(m2.y, h2, acc[5]);
        acc[6] = fmaf(m2.z, h2, acc[6]); acc[7] = fmaf(m2.w, h2, acc[7]);
    }
#pragma unroll
    for (int s = 0; s < 4; s++) {
        if (jseg == s) {
            if (s == 0) {
#pragma unroll
                for (int q = 0; q < 8; q++) buf[q][col] = acc[q];
            } else {
#pragma unroll
                for (int q = 0; q < 8; q++) buf[q][col] += acc[q];
            }
        }
        __syncthreads();
    }

    // layernorm stats: warps 0..7 -> row wp
    if (wp < 8) {
        float s = 0.f, sq = 0.f;
#pragma unroll
        for (int c = 0; c < 4; c++) {
            float v = buf[wp][lane + c * 32];
            s += v; sq = fmaf(v, v, sq);
        }
#pragma unroll
        for (int o = 16; o > 0; o >>= 1) {
            s += __shfl_xor_sync(0xffffffff, s, o);
            sq += __shfl_xor_sync(0xffffffff, sq, o);
        }
        if (lane == 0) {
            float mean = s * (1.f / GH);
            float var = sq * (1.f / GH) - mean * mean;
            stat[wp][0] = mean;
            stat[wp][1] = rsqrtf(var + EPS);
        }
    }
    __syncthreads();
    // normalize + relu + transpose into bufT
    for (int idx = t; idx < 8 * GH; idx += 512) {
        int r = idx & 7, cc = idx >> 3;
        float v = (buf[r][cc] - stat[r][0]) * stat[r][1] * norm_g[cc] + norm_b[cc];
        bufT[cc * 12 + r] = fmaxf(v, 0.f);
    }
    __syncthreads();

    // MLP layer 1 (rg = jseg, 2 rows each)
    float a0, a1;
    a0 = a1 = lab[col];
#pragma unroll 8
    for (int k = 0; k < GH; k++) {
        float w = law[k * GH + col];
        float2 x = *(const float2*)&bufT[k * 12 + jseg * 2];
        a0 = fmaf(x.x, w, a0); a1 = fmaf(x.y, w, a1);
    }
    __syncthreads();
    *(float2*)&bufT[col * 12 + jseg * 2] = make_float2(fmaxf(a0, 0.f), fmaxf(a1, 0.f));
    __syncthreads();

    // MLP layer 2 + H +=
    a0 = a1 = lbb[col];
#pragma unroll 8
    for (int k = 0; k < GH; k++) {
        float w = lbw[k * GH + col];
        float2 x = *(const float2*)&bufT[k * 12 + jseg * 2];
        a0 = fmaf(x.x, w, a0); a1 = fmaf(x.y, w, a1);
    }
    int base = ((b << 8) + i0 + jseg * 2) * GH + col;
    g_H[base] += a0; g_H[base + GH] += a1;
}

// ---------------- K4: phi MLP (512 threads, 8 rows, 4 rows/thread) ----------------
__global__ void __launch_bounds__(512) k_phi(const float* __restrict__ w1, const float* __restrict__ b1,
                                             const float* __restrict__ w2, const float* __restrict__ b2) {
    int r0 = blockIdx.x * 8;
    int t = threadIdx.x;
    int col = t & 255, rg = t >> 8;   // rg 0/1, rows rg*4..rg*4+3
    __shared__ __align__(16) float hT[GH * 12];
    __shared__ __align__(16) float h1T[PHI * 12];

    for (int idx = t; idx < 8 * GH; idx += 512) {
        int rr = idx >> 7, kk = idx & 127;
        hT[kk * 12 + rr] = g_H[(r0 + rr) * GH + kk];
    }
    __syncthreads();
    float a0, a1, a2, a3;
    a0 = a1 = a2 = a3 = b1[col];
#pragma unroll 8
    for (int k = 0; k < GH; k++) {
        float w = w1[k * PHI + col];
        float4 x = *(const float4*)&hT[k * 12 + rg * 4];
        a0 = fmaf(x.x, w, a0); a1 = fmaf(x.y, w, a1);
        a2 = fmaf(x.z, w, a2); a3 = fmaf(x.w, w, a3);
    }
    *(float4*)&h1T[col * 12 + rg * 4] =
        make_float4(fmaxf(a0, 0.f), fmaxf(a1, 0.f), fmaxf(a2, 0.f), fmaxf(a3, 0.f));
    __syncthreads();
    a0 = a1 = a2 = a3 = b2[col];
#pragma unroll 8
    for (int k = 0; k < PHI; k++) {
        float w = w2[k * PHI + col];
        float4 x = *(const float4*)&h1T[k * 12 + rg * 4];
        a0 = fmaf(x.x, w, a0); a1 = fmaf(x.y, w, a1);
        a2 = fmaf(x.z, w, a2); a3 = fmaf(x.w, w, a3);
    }
    int base = (r0 + rg * 4) * PHI + col;
    g_phi[base] = fmaxf(a0, 0.f);
    g_phi[base + PHI] = fmaxf(a1, 0.f);
    g_phi[base + 2 * PHI] = fmaxf(a2, 0.f);
    g_phi[base + 3 * PHI] = fmaxf(a3, 0.f);
}

// ---------------- K5: masked pooling (8 segments of 32 nodes) ----------------
__global__ void k_pool(const float* __restrict__ home_mask) {
    int b = blockIdx.x;
    int seg = blockIdx.y;
    int p = threadIdx.x;          // 256
    const float* pb = g_phi + b * N * PHI;
    const float* hm = home_mask + b * N;
    float hs = 0.f, as = 0.f;
    int n0 = seg * 32;
#pragma unroll 8
    for (int n = n0; n < n0 + 32; n++) {
        float v = pb[n * PHI + p];
        float m = hm[n];
        hs = fmaf(v, m, hs);
        as = fmaf(v, 1.f - m, as);
    }
    g_sums[((seg * 2 + 0) * B + b) * PHI + p] = hs;
    g_sums[((seg * 2 + 1) * B + b) * PHI + p] = as;
}

// ---------------- K6: rho head ----------------
__global__ void k_rho(const float* __restrict__ w1, const float* __restrict__ b1,
                      const float* __restrict__ w2, float* __restrict__ out) {
    int b = blockIdx.x;           // 8
    int t = threadIdx.x;          // 128
    __shared__ float hs[PHI];
    __shared__ float as[PHI];
    __shared__ float red[RHO];
    for (int c = t; c < PHI; c += 128) {
        float h = 0.f, a = 0.f;
#pragma unroll
        for (int seg = 0; seg < 8; seg++) {
            h += g_sums[((seg * 2 + 0) * B + b) * PHI + c];
            a += g_sums[((seg * 2 + 1) * B + b) * PHI + c];
        }
        hs[c] = h; as[c] = a;
    }
    __syncthreads();
    float rh = b1[t], ra = b1[t];
#pragma unroll 8
    for (int k = 0; k < PHI; k++) {
        float w = w1[k * RHO + t];
        rh = fmaf(hs[k], w, rh);
        ra = fmaf(as[k], w, ra);
    }
    rh = fmaxf(rh, 0.f);
    ra = fmaxf(ra, 0.f);
    red[t] = (rh - ra) * w2[t];
    __syncthreads();
    for (int s = RHO / 2; s > 0; s >>= 1) {
        if (t < s) red[t] += red[t + s];
        __syncthreads();
    }
    if (t == 0) out[b] = 0.5f + 0.5f * tanhf(red[0]);
}

// ---------------- launch ----------------
extern "C" void kernel_launch(void* const* d_in, const int* in_sizes, int n_in,
                              void* d_out, int out_size) {
    const float* A        = (const float*)d_in[0];
    const float* X        = (const float*)d_in[1];
    const float* home     = (const float*)d_in[2];
    const float* emb1_w   = (const float*)d_in[3];
    const float* emb1_b   = (const float*)d_in[4];
    const float* emb2_w   = (const float*)d_in[5];
    const float* emb2_b   = (const float*)d_in[6];
    const float* rgcn_w0  = (const float*)d_in[7];
    const float* root0    = (const float*)d_in[8];
    const float* bias0    = (const float*)d_in[9];
    const float* law0     = (const float*)d_in[10];
    const float* lab0     = (const float*)d_in[11];
    const float* lbw0     = (const float*)d_in[12];
    const float* lbb0     = (const float*)d_in[13];
    const float* rgcn_w1  = (const float*)d_in[14];
    const float* root1    = (const float*)d_in[15];
    const float* bias1    = (const float*)d_in[16];
    const float* law1     = (const float*)d_in[17];
    const float* lab1     = (const float*)d_in[18];
    const float* lbw1     = (const float*)d_in[19];
    const float* lbb1     = (const float*)d_in[20];
    const float* norm_g   = (const float*)d_in[21];
    const float* norm_b   = (const float*)d_in[22];
    const float* phi_w1   = (const float*)d_in[23];
    const float* phi_b1   = (const float*)d_in[24];
    const float* phi_w2   = (const float*)d_in[25];
    const float* phi_b2   = (const float*)d_in[26];
    const float* rho_w1   = (const float*)d_in[27];
    const float* rho_b1   = (const float*)d_in[28];
    const float* rho_w2   = (const float*)d_in[29];
    float* out = (float*)d_out;

    dim3 pgrid(8, 8);
    k_prep<<<pgrid, 256>>>(A);
    k_emb<<<256, 512>>>(X, emb1_w, emb1_b, emb2_w, emb2_b);

    k_rgcn<<<256, 512>>>(rgcn_w0, root0, bias0);
    k_scat<<<256, 512>>>(A, norm_g, norm_b, law0, lab0, lbw0, lbb0);

    k_rgcn<<<256, 512>>>(rgcn_w1, root1, bias1);
    k_scat<<<256, 512>>>(A, norm_g, norm_b, law1, lab1, lbw1, lbb1);

    k_phi<<<256, 512>>>(phi_w1, phi_b1, phi_w2, phi_b2);
    dim3 pg(B, 8);
    k_pool<<<pg, 256>>>(home);
    k_rho<<<B, 128>>>(rho_w1, rho_b1, rho_w2, out);
}

// round 8
// speedup vs baseline: 1.1779x; 1.0065x over previous
#include <cuda_runtime.h>
#include <math.h>

#define B 8
#define N 256
#define BN 2048
#define NID 64
#define V 128
#define GH 128
#define PHI 256
#define RHO 128
#define EPS 1e-5f

// ---------------- scratch ----------------
__device__ float g_H[BN * GH];
__device__ float g_H2[BN * GH];
__device__ float g_phi[BN * PHI];
__device__ float g_sums[8 * 2 * B * PHI];
__device__ float g_msk[BN * N];      // sign(A) in {-1,0,1}, layout [b][i][j]
__device__ float2 g_rcp[BN];         // (1/max(cntPos,1), 1/max(cntNeg,1)) per target j

// ---------------- K0: prep  masks + counts ----------------
__global__ void k_prep(const float* __restrict__ A) {
    int b = blockIdx.x, jc = blockIdx.y * 32;
    int t = threadIdx.x;              // 256
    int j = jc + (t & 31), iseg = t >> 5;   // 8 segs of 32 i
    const float* Ab = A + b * N * N;
    float cp = 0.f, cn = 0.f;
#pragma unroll 4
    for (int ii = 0; ii < 32; ii++) {
        int i = iseg * 32 + ii;
        float a = Ab[i * N + j];
        float p = (a > 0.f) ? 1.f : 0.f;
        float n = (a < 0.f) ? 1.f : 0.f;
        cp += p; cn += n;
        g_msk[((b << 8) + i) * N + j] = p - n;
    }
    __shared__ float sp[8][32], sn[8][32];
    sp[iseg][t & 31] = cp; sn[iseg][t & 31] = cn;
    __syncthreads();
    if (t < 32) {
        float tp = 0.f, tn = 0.f;
#pragma unroll
        for (int s = 0; s < 8; s++) { tp += sp[s][t]; tn += sn[s][t]; }
        g_rcp[(b << 8) + jc + t] = make_float2(1.f / fmaxf(tp, 1.f), 1.f / fmaxf(tn, 1.f));
    }
}

// ---------------- K1: embedding (512 thr, 8 rows, 2 rows/thread) ----------------
__global__ void __launch_bounds__(512) k_emb(const float* __restrict__ X,
                      const float* __restrict__ W1, const float* __restrict__ b1,
                      const float* __restrict__ W2, const float* __restrict__ b2) {
    int r0 = blockIdx.x * 8;
    int t = threadIdx.x;
    int col = t & 127, rg = t >> 7;   // rg 0..3, rows rg*2, rg*2+1
    __shared__ __align__(16) float xsT[NID * 12];
    __shared__ __align__(16) float h1T[V * 12];

    if (t < 8 * NID) {
        int rr = t >> 6, kk = t & 63;
        xsT[kk * 12 + rr] = X[(r0 + rr) * NID + kk];
    }
    __syncthreads();
    float a0, a1;
    a0 = a1 = b1[col];
#pragma unroll 8
    for (int k = 0; k < NID; k++) {
        float w = W1[k * V + col];
        float2 x = *(const float2*)&xsT[k * 12 + rg * 2];
        a0 = fmaf(x.x, w, a0); a1 = fmaf(x.y, w, a1);
    }
    *(float2*)&h1T[col * 12 + rg * 2] = make_float2(fmaxf(a0, 0.f), fmaxf(a1, 0.f));
    __syncthreads();
    a0 = a1 = b2[col];
#pragma unroll 8
    for (int k = 0; k < V; k++) {
        float w = W2[k * V + col];
        float2 x = *(const float2*)&h1T[k * 12 + rg * 2];
        a0 = fmaf(x.x, w, a0); a1 = fmaf(x.y, w, a1);
    }
    int base = (r0 + rg * 2) * V + col;
    g_H[base] = a0; g_H[base + V] = a1;
}

// ---------------- K2: fused RGCN (masked-mean reduce + 3-way matmul) ----------------
// block = (b, j-tile of 8); 512 threads = 4 i-segments x 128 cols
__global__ void __launch_bounds__(512) k_rgcn(const float* __restrict__ Wrel,
                                              const float* __restrict__ Wroot,
                                              const float* __restrict__ bias) {
    int b = blockIdx.x >> 5;
    int j0 = (blockIdx.x & 31) * 8;
    int t = threadIdx.x;
    int col = t & 127, iseg = t >> 7;     // 0..3
    __shared__ __align__(16) float msk_s[N][8];     // 8KB
    __shared__ float sAccS[8][128], sAccA[8][128];  // 8KB
    __shared__ __align__(16) float hrT[GH * 12];    // 6KB
    __shared__ __align__(16) float snT[GH * 12];
    __shared__ __align__(16) float spT[GH * 12];
    __shared__ float2 rcp_s[8];

    for (int idx = t; idx < N * 8; idx += 512) {
        int i = idx >> 3, jj = idx & 7;
        msk_s[i][jj] = g_msk[((b << 8) + i) * N + j0 + jj];
    }
    if (t < 8) rcp_s[t] = g_rcp[(b << 8) + j0 + t];
    __syncthreads();

    float accS[8], accA[8];
#pragma unroll
    for (int jj = 0; jj < 8; jj++) { accS[jj] = 0.f; accA[jj] = 0.f; }
    const float* Hb = g_H + ((b << 8) + (iseg << 6)) * V + col;
    // explicit prefetch-batched mainloop: 16 independent LDGs, then FMAs
    for (int c = 0; c < 64; c += 16) {
        float hv[16];
#pragma unroll
        for (int u = 0; u < 16; u++) hv[u] = Hb[(c + u) * V];
#pragma unroll
        for (int u = 0; u < 16; u++) {
            float h = hv[u];
            int i = (iseg << 6) + c + u;
            float4 m1 = *(const float4*)&msk_s[i][0];
            float4 m2 = *(const float4*)&msk_s[i][4];
            accS[0] = fmaf(m1.x, h, accS[0]); accA[0] = fmaf(fabsf(m1.x), h, accA[0]);
            accS[1] = fmaf(m1.y, h, accS[1]); accA[1] = fmaf(fabsf(m1.y), h, accA[1]);
            accS[2] = fmaf(m1.z, h, accS[2]); accA[2] = fmaf(fabsf(m1.z), h, accA[2]);
            accS[3] = fmaf(m1.w, h, accS[3]); accA[3] = fmaf(fabsf(m1.w), h, accA[3]);
            accS[4] = fmaf(m2.x, h, accS[4]); accA[4] = fmaf(fabsf(m2.x), h, accA[4]);
            accS[5] = fmaf(m2.y, h, accS[5]); accA[5] = fmaf(fabsf(m2.y), h, accA[5]);
            accS[6] = fmaf(m2.z, h, accS[6]); accA[6] = fmaf(fabsf(m2.z), h, accA[6]);
            accS[7] = fmaf(m2.w, h, accS[7]); accA[7] = fmaf(fabsf(m2.w), h, accA[7]);
        }
    }
    // 4-pass combine into sAcc
#pragma unroll
    for (int s = 0; s < 4; s++) {
        if (iseg == s) {
            if (s == 0) {
#pragma unroll
                for (int jj = 0; jj < 8; jj++) { sAccS[jj][col] = accS[jj]; sAccA[jj][col] = accA[jj]; }
            } else {
#pragma unroll
                for (int jj = 0; jj < 8; jj++) { sAccS[jj][col] += accS[jj]; sAccA[jj][col] += accA[jj]; }
            }
        }
        __syncthreads();
    }
    // normalize + transpose (iseg 0), stage H rows (all threads)
    if (iseg == 0) {
#pragma unroll
        for (int jj = 0; jj < 8; jj++) {
            float sa = sAccA[jj][col], ss = sAccS[jj][col];
            spT[col * 12 + jj] = (sa + ss) * 0.5f * rcp_s[jj].x;
            snT[col * 12 + jj] = (sa - ss) * 0.5f * rcp_s[jj].y;
        }
    }
    for (int idx = t; idx < 8 * GH; idx += 512) {
        int rr = idx >> 7, kk = idx & 127;
        hrT[kk * 12 + rr] = g_H[((b << 8) + j0 + rr) * GH + kk];
    }
    __syncthreads();

    // matmul: rg = iseg handles rows rg*2, rg*2+1
    const float* W0 = Wrel;
    const float* W1 = Wrel + V * GH;
    float a0, a1;
    a0 = a1 = bias[col];
#pragma unroll 8
    for (int k = 0; k < GH; k++) {
        float wr = Wroot[k * GH + col];
        float w0 = W0[k * GH + col];
        float w1 = W1[k * GH + col];
        float2 h = *(const float2*)&hrT[k * 12 + iseg * 2];
        float2 sn = *(const float2*)&snT[k * 12 + iseg * 2];
        float2 sp = *(const float2*)&spT[k * 12 + iseg * 2];
        a0 = fmaf(h.x, wr, a0);  a1 = fmaf(h.y, wr, a1);
        a0 = fmaf(sn.x, w0, a0); a1 = fmaf(sn.y, w0, a1);
        a0 = fmaf(sp.x, w1, a0); a1 = fmaf(sp.y, w1, a1);
    }
    int base = ((b << 8) + j0 + iseg * 2) * GH + col;
    g_H2[base] = a0; g_H2[base + GH] = a1;
}

// ---------------- K3: fused scatter + layernorm + MLP + H+= ----------------
// block = (b, i-tile of 8); 512 threads = 4 j-segments x 128 cols
__global__ void __launch_bounds__(512) k_scat(const float* __restrict__ A,
                                              const float* __restrict__ norm_g, const float* __restrict__ norm_b,
                                              const float* __restrict__ law, const float* __restrict__ lab,
                                              const float* __restrict__ lbw, const float* __restrict__ lbb) {
    int b = blockIdx.x >> 5;
    int i0 = (blockIdx.x & 31) * 8;
    int t = threadIdx.x;
    int col = t & 127, jseg = t >> 7;     // 0..3
    int wp = t >> 5, lane = t & 31;
    __shared__ __align__(16) float aabT[N * 8];     // [j][i-in-tile] 8KB
    __shared__ float buf[8][128];                   // 4KB
    __shared__ __align__(16) float bufT[GH * 12];   // 6KB
    __shared__ float stat[8][2];

    // stage |A| transposed: aabT[j][q] = |A[b][i0+q][j]|
    {
        int jj = t & 255, half = t >> 8;   // half: rows 0-3 / 4-7
        const float* Ar = A + (b * N + i0 + half * 4) * N + jj;
        float a_[4];
#pragma unroll
        for (int q = 0; q < 4; q++) a_[q] = fabsf(Ar[q * N]);
        *(float4*)&aabT[jj * 8 + half * 4] = make_float4(a_[0], a_[1], a_[2], a_[3]);
    }
    __syncthreads();

    float acc[8];
#pragma unroll
    for (int q = 0; q < 8; q++) acc[q] = 0.f;
    const float* H2b = g_H2 + ((b << 8) + (jseg << 6)) * GH + col;
    // explicit prefetch-batched mainloop
    for (int c = 0; c < 64; c += 16) {
        float h2v[16];
#pragma unroll
        for (int u = 0; u < 16; u++) h2v[u] = H2b[(c + u) * GH];
#pragma unroll
        for (int u = 0; u < 16; u++) {
            float h2 = h2v[u];
            int j = (jseg << 6) + c + u;
            float4 m1 = *(const float4*)&aabT[j * 8];
            float4 m2 = *(const float4*)&aabT[j * 8 + 4];
            acc[0] = fmaf(m1.x, h2, acc[0]); acc[1] = fmaf(m1.y, h2, acc[1]);
            acc[2] = fmaf(m1.z, h2, acc[2]); acc[3] = fmaf(m1.w, h2, acc[3]);
            acc[4] = fmaf(m2.x, h2, acc[4]); acc[5] = fmaf(m2.y, h2, acc[5]);
            acc[6] = fmaf(m2.z, h2, acc[6]); acc[7] = fmaf(m2.w, h2, acc[7]);
        }
    }
#pragma unroll
    for (int s = 0; s < 4; s++) {
        if (jseg == s) {
            if (s == 0) {
#pragma unroll
                for (int q = 0; q < 8; q++) buf[q][col] = acc[q];
            } else {
#pragma unroll
                for (int q = 0; q < 8; q++) buf[q][col] += acc[q];
            }
        }
        __syncthreads();
    }

    // layernorm stats: warps 0..7 -> row wp
    if (wp < 8) {
        float s = 0.f, sq = 0.f;
#pragma unroll
        for (int c = 0; c < 4; c++) {
            float v = buf[wp][lane + c * 32];
            s += v; sq = fmaf(v, v, sq);
        }
#pragma unroll
        for (int o = 16; o > 0; o >>= 1) {
            s += __shfl_xor_sync(0xffffffff, s, o);
            sq += __shfl_xor_sync(0xffffffff, sq, o);
        }
        if (lane == 0) {
            float mean = s * (1.f / GH);
            float var = sq * (1.f / GH) - mean * mean;
            stat[wp][0] = mean;
            stat[wp][1] = rsqrtf(var + EPS);
        }
    }
    __syncthreads();
    // normalize + relu + transpose into bufT
    for (int idx = t; idx < 8 * GH; idx += 512) {
        int r = idx & 7, cc = idx >> 3;
        float v = (buf[r][cc] - stat[r][0]) * stat[r][1] * norm_g[cc] + norm_b[cc];
        bufT[cc * 12 + r] = fmaxf(v, 0.f);
    }
    __syncthreads();

    // MLP layer 1 (rg = jseg, 2 rows each)
    float a0, a1;
    a0 = a1 = lab[col];
#pragma unroll 8
    for (int k = 0; k < GH; k++) {
        float w = law[k * GH + col];
        float2 x = *(const float2*)&bufT[k * 12 + jseg * 2];
        a0 = fmaf(x.x, w, a0); a1 = fmaf(x.y, w, a1);
    }
    __syncthreads();
    *(float2*)&bufT[col * 12 + jseg * 2] = make_float2(fmaxf(a0, 0.f), fmaxf(a1, 0.f));
    __syncthreads();

    // MLP layer 2 + H +=
    a0 = a1 = lbb[col];
#pragma unroll 8
    for (int k = 0; k < GH; k++) {
        float w = lbw[k * GH + col];
        float2 x = *(const float2*)&bufT[k * 12 + jseg * 2];
        a0 = fmaf(x.x, w, a0); a1 = fmaf(x.y, w, a1);
    }
    int base = ((b << 8) + i0 + jseg * 2) * GH + col;
    g_H[base] += a0; g_H[base + GH] += a1;
}

// ---------------- K4: phi MLP (512 threads, 8 rows, 4 rows/thread) ----------------
__global__ void __launch_bounds__(512) k_phi(const float* __restrict__ w1, const float* __restrict__ b1,
                                             const float* __restrict__ w2, const float* __restrict__ b2) {
    int r0 = blockIdx.x * 8;
    int t = threadIdx.x;
    int col = t & 255, rg = t >> 8;   // rg 0/1, rows rg*4..rg*4+3
    __shared__ __align__(16) float hT[GH * 12];
    __shared__ __align__(16) float h1T[PHI * 12];

    for (int idx = t; idx < 8 * GH; idx += 512) {
        int rr = idx >> 7, kk = idx & 127;
        hT[kk * 12 + rr] = g_H[(r0 + rr) * GH + kk];
    }
    __syncthreads();
    float a0, a1, a2, a3;
    a0 = a1 = a2 = a3 = b1[col];
#pragma unroll 8
    for (int k = 0; k < GH; k++) {
        float w = w1[k * PHI + col];
        float4 x = *(const float4*)&hT[k * 12 + rg * 4];
        a0 = fmaf(x.x, w, a0); a1 = fmaf(x.y, w, a1);
        a2 = fmaf(x.z, w, a2); a3 = fmaf(x.w, w, a3);
    }
    *(float4*)&h1T[col * 12 + rg * 4] =
        make_float4(fmaxf(a0, 0.f), fmaxf(a1, 0.f), fmaxf(a2, 0.f), fmaxf(a3, 0.f));
    __syncthreads();
    a0 = a1 = a2 = a3 = b2[col];
#pragma unroll 8
    for (int k = 0; k < PHI; k++) {
        float w = w2[k * PHI + col];
        float4 x = *(const float4*)&h1T[k * 12 + rg * 4];
        a0 = fmaf(x.x, w, a0); a1 = fmaf(x.y, w, a1);
        a2 = fmaf(x.z, w, a2); a3 = fmaf(x.w, w, a3);
    }
    int base = (r0 + rg * 4) * PHI + col;
    g_phi[base] = fmaxf(a0, 0.f);
    g_phi[base + PHI] = fmaxf(a1, 0.f);
    g_phi[base + 2 * PHI] = fmaxf(a2, 0.f);
    g_phi[base + 3 * PHI] = fmaxf(a3, 0.f);
}

// ---------------- K5: masked pooling (8 segments of 32 nodes) ----------------
__global__ void k_pool(const float* __restrict__ home_mask) {
    int b = blockIdx.x;
    int seg = blockIdx.y;
    int p = threadIdx.x;          // 256
    const float* pb = g_phi + b * N * PHI;
    const float* hm = home_mask + b * N;
    float hs = 0.f, as = 0.f;
    int n0 = seg * 32;
#pragma unroll 8
    for (int n = n0; n < n0 + 32; n++) {
        float v = pb[n * PHI + p];
        float m = hm[n];
        hs = fmaf(v, m, hs);
        as = fmaf(v, 1.f - m, as);
    }
    g_sums[((seg * 2 + 0) * B + b) * PHI + p] = hs;
    g_sums[((seg * 2 + 1) * B + b) * PHI + p] = as;
}

// ---------------- K6: rho head ----------------
__global__ void k_rho(const float* __restrict__ w1, const float* __restrict__ b1,
                      const float* __restrict__ w2, float* __restrict__ out) {
    int b = blockIdx.x;           // 8
    int t = threadIdx.x;          // 128
    __shared__ float hs[PHI];
    __shared__ float as[PHI];
    __shared__ float red[RHO];
    for (int c = t; c < PHI; c += 128) {
        float h = 0.f, a = 0.f;
#pragma unroll
        for (int seg = 0; seg < 8; seg++) {
            h += g_sums[((seg * 2 + 0) * B + b) * PHI + c];
            a += g_sums[((seg * 2 + 1) * B + b) * PHI + c];
        }
        hs[c] = h; as[c] = a;
    }
    __syncthreads();
    float rh = b1[t], ra = b1[t];
#pragma unroll 8
    for (int k = 0; k < PHI; k++) {
        float w = w1[k * RHO + t];
        rh = fmaf(hs[k], w, rh);
        ra = fmaf(as[k], w, ra);
    }
    rh = fmaxf(rh, 0.f);
    ra = fmaxf(ra, 0.f);
    red[t] = (rh - ra) * w2[t];
    __syncthreads();
    for (int s = RHO / 2; s > 0; s >>= 1) {
        if (t < s) red[t] += red[t + s];
        __syncthreads();
    }
    if (t == 0) out[b] = 0.5f + 0.5f * tanhf(red[0]);
}

// ---------------- launch ----------------
extern "C" void kernel_launch(void* const* d_in, const int* in_sizes, int n_in,
                              void* d_out, int out_size) {
    const float* A        = (const float*)d_in[0];
    const float* X        = (const float*)d_in[1];
    const float* home     = (const float*)d_in[2];
    const float* emb1_w   = (const float*)d_in[3];
    const float* emb1_b   = (const float*)d_in[4];
    const float* emb2_w   = (const float*)d_in[5];
    const float* emb2_b   = (const float*)d_in[6];
    const float* rgcn_w0  = (const float*)d_in[7];
    const float* root0    = (const float*)d_in[8];
    const float* bias0    = (const float*)d_in[9];
    const float* law0     = (const float*)d_in[10];
    const float* lab0     = (const float*)d_in[11];
    const float* lbw0     = (const float*)d_in[12];
    const float* lbb0     = (const float*)d_in[13];
    const float* rgcn_w1  = (const float*)d_in[14];
    const float* root1    = (const float*)d_in[15];
    const float* bias1    = (const float*)d_in[16];
    const float* law1     = (const float*)d_in[17];
    const float* lab1     = (const float*)d_in[18];
    const float* lbw1     = (const float*)d_in[19];
    const float* lbb1     = (const float*)d_in[20];
    const float* norm_g   = (const float*)d_in[21];
    const float* norm_b   = (const float*)d_in[22];
    const float* phi_w1   = (const float*)d_in[23];
    const float* phi_b1   = (const float*)d_in[24];
    const float* phi_w2   = (const float*)d_in[25];
    const float* phi_b2   = (const float*)d_in[26];
    const float* rho_w1   = (const float*)d_in[27];
    const float* rho_b1   = (const float*)d_in[28];
    const float* rho_w2   = (const float*)d_in[29];
    float* out = (float*)d_out;

    dim3 pgrid(8, 8);
    k_prep<<<pgrid, 256>>>(A);
    k_emb<<<256, 512>>>(X, emb1_w, emb1_b, emb2_w, emb2_b);

    k_rgcn<<<256, 512>>>(rgcn_w0, root0, bias0);
    k_scat<<<256, 512>>>(A, norm_g, norm_b, law0, lab0, lbw0, lbb0);

    k_rgcn<<<256, 512>>>(rgcn_w1, root1, bias1);
    k_scat<<<256, 512>>>(A, norm_g, norm_b, law1, lab1, lbw1, lbb1);

    k_phi<<<256, 512>>>(phi_w1, phi_b1, phi_w2, phi_b2);
    dim3 pg(B, 8);
    k_pool<<<pg, 256>>>(home);
    k_rho<<<B, 128>>>(rho_w1, rho_b1, rho_w2, out);
}